// round 7
// baseline (speedup 1.0000x reference)
#include <cuda_runtime.h>
#include <cuda_bf16.h>
#include <math.h>

// Problem constants
#define BB   64     // batch
#define TT   512    // time
#define EE   256    // embedding
#define HH   256    // hidden
#define G4   1024   // 4*H
#define KK   10     // tags

// -------- device scratch (allocation-free rule: static device globals) -----
__device__ float g_pre[2u * 32768u * 1024u];          // [dir][t*64+b][4H]
__device__ float g_h[2u * 512u * 64u * 256u];         // [dir][t][b][h]
__device__ float g_logits[512u * 64u * 10u];          // [t][b][k]

// -------- f32x2 packed helpers ----------------------------------------------
__device__ __forceinline__ unsigned long long pk2(float x, float y) {
    unsigned long long r;
    asm("mov.b64 %0, {%1,%2};" : "=l"(r) : "f"(x), "f"(y));
    return r;
}
__device__ __forceinline__ void fma2(unsigned long long& d,
                                     unsigned long long a,
                                     unsigned long long b) {
    asm("fma.rn.f32x2 %0, %1, %2, %0;" : "+l"(d) : "l"(a), "l"(b));
}
__device__ __forceinline__ float2 up2(unsigned long long v) {
    float2 r;
    asm("mov.b64 {%0,%1}, %2;" : "=f"(r.x), "=f"(r.y) : "l"(v));
    return r;
}

__device__ __forceinline__ unsigned smem_u32(const void* p) {
    unsigned a;
    asm("{ .reg .u64 t; cvta.to.shared.u64 t, %1; cvt.u32.u64 %0, t; }"
        : "=r"(a) : "l"(p));
    return a;
}
__device__ __forceinline__ unsigned mapa_u32(unsigned laddr, unsigned peer) {
    unsigned r;
    asm("mapa.shared::cluster.u32 %0, %1, %2;" : "=r"(r) : "r"(laddr), "r"(peer));
    return r;
}
__device__ __forceinline__ void st_cluster_v4(unsigned addr, float4 v) {
    asm volatile("st.shared::cluster.v4.f32 [%0], {%1,%2,%3,%4};"
                 :: "r"(addr), "f"(v.x), "f"(v.y), "f"(v.z), "f"(v.w)
                 : "memory");
}

// ---------------------------------------------------------------------------
// Dummy kernels: shift pregemm_kernel into ncu's captured launch slot (4th).
// ---------------------------------------------------------------------------
__global__ void dummy_kernel() {}

// ---------------------------------------------------------------------------
// Kernel A: fused embedding-gather + GEMM:  g_pre = emb[sent] @ Wih^T + bias
// (BYTE-IDENTICAL to R6 — being profiled this round, do not perturb.)
// ---------------------------------------------------------------------------
__global__ void __launch_bounds__(256)
pregemm_kernel(const int* __restrict__ sent,
               const float* __restrict__ emb,
               const float* __restrict__ Wih_f,
               const float* __restrict__ b_f,
               const float* __restrict__ Wih_b,
               const float* __restrict__ b_b) {
    const int dir = blockIdx.z;
    const int n0  = blockIdx.x * 128;
    const int m0  = blockIdx.y * 128;
    const float* Wih  = dir ? Wih_b : Wih_f;
    const float* bias = dir ? b_b  : b_f;

    __shared__ float As[2][16][128];
    __shared__ float Bs[2][16][128];
    __shared__ int   toks[128];

    const int tid = threadIdx.x;
    if (tid < 128) {
        int m = m0 + tid;                 // m = t*64 + b
        toks[tid] = sent[(m & 63) * TT + (m >> 6)];
    }
    __syncthreads();

    const int mA   = tid & 127;
    const int half = tid >> 7;
    const int ty   = tid >> 4;
    const int tx   = tid & 15;

    const float4* emb4 = (const float4*)emb;
    const float4* w4   = (const float4*)Wih;

    const size_t arow = (size_t)toks[mA] * 64;
    const size_t brow = (size_t)(n0 + mA) * 64;

    float acc[8][8];
#pragma unroll
    for (int i = 0; i < 8; ++i)
#pragma unroll
        for (int j = 0; j < 8; ++j) acc[i][j] = 0.f;

    float4 a0g = emb4[arow + half * 2 + 0];
    float4 a1g = emb4[arow + half * 2 + 1];
    float4 b0g = w4  [brow + half * 2 + 0];
    float4 b1g = w4  [brow + half * 2 + 1];

    int buf = 0;
    {
        const int kb = half * 8;
        As[0][kb+0][mA]=a0g.x; As[0][kb+1][mA]=a0g.y; As[0][kb+2][mA]=a0g.z; As[0][kb+3][mA]=a0g.w;
        As[0][kb+4][mA]=a1g.x; As[0][kb+5][mA]=a1g.y; As[0][kb+6][mA]=a1g.z; As[0][kb+7][mA]=a1g.w;
        Bs[0][kb+0][mA]=b0g.x; Bs[0][kb+1][mA]=b0g.y; Bs[0][kb+2][mA]=b0g.z; Bs[0][kb+3][mA]=b0g.w;
        Bs[0][kb+4][mA]=b1g.x; Bs[0][kb+5][mA]=b1g.y; Bs[0][kb+6][mA]=b1g.z; Bs[0][kb+7][mA]=b1g.w;
    }
    __syncthreads();

    for (int kc = 0; kc < 16; ++kc) {
        if (kc < 15) {
            const size_t kq = (size_t)(kc + 1) * 4 + half * 2;
            a0g = emb4[arow + kq];  a1g = emb4[arow + kq + 1];
            b0g = w4  [brow + kq];  b1g = w4  [brow + kq + 1];
        }
#pragma unroll
        for (int kk = 0; kk < 16; ++kk) {
            float4 aA = *(const float4*)&As[buf][kk][ty * 8];
            float4 aB = *(const float4*)&As[buf][kk][ty * 8 + 4];
            float4 bA = *(const float4*)&Bs[buf][kk][tx * 8];
            float4 bB = *(const float4*)&Bs[buf][kk][tx * 8 + 4];
            float av[8] = {aA.x, aA.y, aA.z, aA.w, aB.x, aB.y, aB.z, aB.w};
            float bv[8] = {bA.x, bA.y, bA.z, bA.w, bB.x, bB.y, bB.z, bB.w};
#pragma unroll
            for (int i = 0; i < 8; ++i)
#pragma unroll
                for (int j = 0; j < 8; ++j)
                    acc[i][j] += av[i] * bv[j];
        }
        if (kc < 15) {
            const int nb = buf ^ 1;
            const int kb = half * 8;
            As[nb][kb+0][mA]=a0g.x; As[nb][kb+1][mA]=a0g.y; As[nb][kb+2][mA]=a0g.z; As[nb][kb+3][mA]=a0g.w;
            As[nb][kb+4][mA]=a1g.x; As[nb][kb+5][mA]=a1g.y; As[nb][kb+6][mA]=a1g.z; As[nb][kb+7][mA]=a1g.w;
            Bs[nb][kb+0][mA]=b0g.x; Bs[nb][kb+1][mA]=b0g.y; Bs[nb][kb+2][mA]=b0g.z; Bs[nb][kb+3][mA]=b0g.w;
            Bs[nb][kb+4][mA]=b1g.x; Bs[nb][kb+5][mA]=b1g.y; Bs[nb][kb+6][mA]=b1g.z; Bs[nb][kb+7][mA]=b1g.w;
            __syncthreads();
            buf = nb;
        }
    }

    float4 bv0 = ((const float4*)bias)[(n0 >> 2) + tx * 2];
    float4 bv1 = ((const float4*)bias)[(n0 >> 2) + tx * 2 + 1];
    float4* out4 = (float4*)g_pre;
#pragma unroll
    for (int i = 0; i < 8; ++i) {
        const int m = m0 + ty * 8 + i;
        const size_t row = (size_t)dir * 32768 + m;
        float4 o0, o1;
        o0.x = acc[i][0] + bv0.x; o0.y = acc[i][1] + bv0.y;
        o0.z = acc[i][2] + bv0.z; o0.w = acc[i][3] + bv0.w;
        o1.x = acc[i][4] + bv1.x; o1.y = acc[i][5] + bv1.y;
        o1.z = acc[i][6] + bv1.z; o1.w = acc[i][7] + bv1.w;
        out4[row * 256 + (n0 >> 2) + tx * 2]     = o0;
        out4[row * 256 + (n0 >> 2) + tx * 2 + 1] = o1;
    }
}

// ---------------------------------------------------------------------------
// Kernel B: cluster-based recurrence. Changes vs R6:
//  - inner-loop fma2 order a0..a3,a0..a3 (RAW distance 4 >= lat)
//  - split cluster barrier: arrive after DSMEM push, g_h STG between
//    arrive and wait (overlaps peer arrival with global store latency)
// ---------------------------------------------------------------------------
#define SW_PITCH 260
#define SH_PITCH 268
#define OFF_SH   (4 * 32 * SW_PITCH)
#define OFF_STG  (OFF_SH + 2 * 8 * SH_PITCH)
#define REC_SMEM_BYTES ((OFF_STG + 256) * 4)

__device__ __forceinline__ float sigm(float x) { return 1.f / (1.f + expf(-x)); }

__global__ void __cluster_dims__(8, 1, 1)
lstm_rec_kernel(const float* __restrict__ Whh_f,
                const float* __restrict__ Whh_b) {
    const int cid    = blockIdx.x >> 3;
    const int r      = blockIdx.x & 7;
    const int dir    = cid >> 3;
    const int bgroup = cid & 7;
    const int tid    = threadIdx.x;       // 256
    const int u      = tid >> 3;
    const int bl     = tid & 7;
    const int bglob  = bgroup * 8 + bl;
    const int hu     = r * 32 + u;

    const float* Whh = dir ? Whh_b : Whh_f;

    extern __shared__ float sm[];
    float* sW   = sm;
    float* sH   = sm + OFF_SH;
    float* sStg = sm + OFF_STG;

    const float4* whh4 = (const float4*)Whh;
    for (int e = tid; e < 8192; e += 256) {
        int g = e >> 11, rem = e & 2047, uu = rem >> 6, k4 = rem & 63;
        float4 v = whh4[(size_t)(g * 256 + r * 32 + uu) * 64 + k4];
        *(float4*)&sW[(g * 32 + uu) * SW_PITCH + k4 * 4] = v;
    }
    for (int e = tid; e < 8 * SH_PITCH; e += 256) sH[e] = 0.f;
    __syncthreads();

    asm volatile("barrier.cluster.arrive.aligned;" ::: "memory");
    asm volatile("barrier.cluster.wait.aligned;" ::: "memory");

    const unsigned sh_base = smem_u32(sH);

    const ulonglong2* w0 = (const ulonglong2*)&sW[(0 * 32 + u) * SW_PITCH];
    const ulonglong2* w1 = (const ulonglong2*)&sW[(1 * 32 + u) * SW_PITCH];
    const ulonglong2* w2 = (const ulonglong2*)&sW[(2 * 32 + u) * SW_PITCH];
    const ulonglong2* w3 = (const ulonglong2*)&sW[(3 * 32 + u) * SW_PITCH];

    const int t0 = dir ? 511 : 0;
    size_t pb = ((size_t)dir * 32768 + (size_t)t0 * 64 + bglob) * 1024 + hu;
    float4 pr;
    pr.x = __ldcg(&g_pre[pb]);
    pr.y = __ldcg(&g_pre[pb + 256]);
    pr.z = __ldcg(&g_pre[pb + 512]);
    pr.w = __ldcg(&g_pre[pb + 768]);

    float c = 0.f;

    for (int it = 0; it < 512; ++it) {
        const int t = dir ? (511 - it) : it;
        const int p = it & 1;

        unsigned long long a0 = pk2(pr.x, 0.f);
        unsigned long long a1 = pk2(pr.y, 0.f);
        unsigned long long a2 = pk2(pr.z, 0.f);
        unsigned long long a3 = pk2(pr.w, 0.f);

        if (it < 511) {
            const int tn = dir ? (t - 1) : (t + 1);
            size_t pbn = ((size_t)dir * 32768 + (size_t)tn * 64 + bglob) * 1024 + hu;
            pr.x = __ldcg(&g_pre[pbn]);
            pr.y = __ldcg(&g_pre[pbn + 256]);
            pr.z = __ldcg(&g_pre[pbn + 512]);
            pr.w = __ldcg(&g_pre[pbn + 768]);
        }

        const ulonglong2* hrow = (const ulonglong2*)&sH[(p * 8 + bl) * SH_PITCH];

#pragma unroll 8
        for (int k4 = 0; k4 < 64; ++k4) {
            ulonglong2 h2 = hrow[k4];
            ulonglong2 v0 = w0[k4];
            ulonglong2 v1 = w1[k4];
            ulonglong2 v2 = w2[k4];
            ulonglong2 v3 = w3[k4];
            fma2(a0, v0.x, h2.x); fma2(a1, v1.x, h2.x);
            fma2(a2, v2.x, h2.x); fma2(a3, v3.x, h2.x);
            fma2(a0, v0.y, h2.y); fma2(a1, v1.y, h2.y);
            fma2(a2, v2.y, h2.y); fma2(a3, v3.y, h2.y);
        }

        float2 q;
        q = up2(a0); float gi = q.x + q.y;
        q = up2(a1); float gf = q.x + q.y;
        q = up2(a2); float gg = q.x + q.y;
        q = up2(a3); float go = q.x + q.y;

        float iv = sigm(gi), fv = sigm(gf), gv = tanhf(gg), ov = sigm(go);
        c = fv * c + iv * gv;
        float hval = ov * tanhf(c);

        sStg[bl * 32 + u] = hval;
        __syncthreads();

        if (it < 511) {
            const float4* stg4 = (const float4*)sStg;
#pragma unroll
            for (int e = tid; e < 512; e += 256) {
                int peer = e >> 6, f4i = e & 63;
                int bb = f4i >> 3, uq = f4i & 7;
                float4 v = stg4[f4i];
                unsigned laddr = sh_base
                               + (unsigned)(((p ^ 1) * 8 + bb) * SH_PITCH * 4)
                               + (unsigned)(r * 128 + uq * 16);
                st_cluster_v4(mapa_u32(laddr, (unsigned)peer), v);
            }
            asm volatile("barrier.cluster.arrive.aligned;" ::: "memory");
            // overlap: global h store while peers arrive
            g_h[(((size_t)(dir * 512 + t)) * 64 + bglob) * 256 + hu] = hval;
            asm volatile("barrier.cluster.wait.aligned;" ::: "memory");
        } else {
            g_h[(((size_t)(dir * 512 + t)) * 64 + bglob) * 256 + hu] = hval;
        }
    }

    asm volatile("barrier.cluster.arrive.aligned;" ::: "memory");
    asm volatile("barrier.cluster.wait.aligned;" ::: "memory");
}

// ---------------------------------------------------------------------------
// Kernel C: logits = concat(h_f, h_b) @ W_out^T + b_out.  grid 512(t), 640 thr
// ---------------------------------------------------------------------------
__global__ void logits_kernel(const float* __restrict__ Wout,
                              const float* __restrict__ bout) {
    const int t = blockIdx.x;
    __shared__ float sWo[10 * 512];
    __shared__ float sCH[64 * 65];
    __shared__ float sBo[10];

    const int tid = threadIdx.x;      // 640
    for (int idx = tid; idx < 5120; idx += 640) sWo[idx] = Wout[idx];
    if (tid < 10) sBo[tid] = bout[tid];

    const int n = tid / 64, bb = tid & 63;
    float acc = 0.f;
    const float4* gh4 = (const float4*)g_h;

    for (int ch = 0; ch < 8; ++ch) {
        __syncthreads();
        for (int idx = tid; idx < 1024; idx += 640) {
            int b_ = idx >> 4, q = idx & 15;
            int d = ch >> 2;
            int hid4 = (ch & 3) * 16 + q;
            float4 v = gh4[(((size_t)d * 512 + t) * 64 + b_) * 64 + hid4];
            float* dst = &sCH[(q * 4) * 65 + b_];
            dst[0]   = v.x;  dst[65]  = v.y;
            dst[130] = v.z;  dst[195] = v.w;
        }
        __syncthreads();
#pragma unroll 8
        for (int r = 0; r < 64; ++r)
            acc += sWo[n * 512 + ch * 64 + r] * sCH[r * 65 + bb];
    }
    g_logits[((size_t)t * 64 + bb) * 10 + n] = acc + sBo[n];
}

// ---------------------------------------------------------------------------
// Kernel D: Viterbi. grid 16 blocks x 128 threads (4 batches/block).
// ---------------------------------------------------------------------------
__global__ void viterbi_kernel(const float* __restrict__ trans,
                               float* __restrict__ out) {
    const int tid  = threadIdx.x;
    const int w    = tid >> 5;
    const int lane = tid & 31;
    const int b    = blockIdx.x * 4 + w;

    __shared__ float         sLT[2][16][4][10];
    __shared__ float         sCur[4][32];
    __shared__ unsigned char bp[4][512][10];
    __shared__ float         tr[100];

    for (int i = tid; i < 100; i += 128) tr[i] = trans[i];

    const int bbase = blockIdx.x * 4;
    float stage[5];
#pragma unroll
    for (int s = 0; s < 5; ++s) {
        int idx = tid + s * 128;
        int t_off = idx / 40, rem = idx % 40;
        int b_off = rem / 10, k = rem % 10;
        stage[s] = g_logits[((size_t)(0 + t_off) * 64 + bbase + b_off) * 10 + k];
    }
#pragma unroll
    for (int s = 0; s < 5; ++s) {
        int idx = tid + s * 128;
        int t_off = idx / 40, rem = idx % 40;
        int b_off = rem / 10, k = rem % 10;
        sLT[0][t_off][b_off][k] = stage[s];
    }
    __syncthreads();

    float trc[10];
#pragma unroll
    for (int i = 0; i < 10; ++i) trc[i] = (lane < 10) ? tr[i * 10 + lane] : 0.f;

    float cur = (lane < 10) ? sLT[0][0][w][lane] : -1e30f;

    for (int cchunk = 0; cchunk < 32; ++cchunk) {
        const int buf = cchunk & 1;
        if (cchunk < 31) {
            const int tb = (cchunk + 1) * 16;
#pragma unroll
            for (int s = 0; s < 5; ++s) {
                int idx = tid + s * 128;
                int t_off = idx / 40, rem = idx % 40;
                int b_off = rem / 10, k = rem % 10;
                stage[s] = g_logits[((size_t)(tb + t_off) * 64 + bbase + b_off) * 10 + k];
            }
        }

        const int tstart = (cchunk == 0) ? 1 : 0;
#pragma unroll 4
        for (int ti = tstart; ti < 16; ++ti) {
            const int t = cchunk * 16 + ti;
            if (lane < 10) sCur[w][lane] = cur;
            __syncwarp();
            float best = sCur[w][0] + trc[0];
            int bi = 0;
#pragma unroll
            for (int i = 1; i < 10; ++i) {
                float v = sCur[w][i] + trc[i];
                if (v > best) { best = v; bi = i; }
            }
            __syncwarp();
            if (lane < 10) {
                cur = sLT[buf][ti][w][lane] + best;
                bp[w][t][lane] = (unsigned char)bi;
            }
        }

        if (cchunk < 31) {
            __syncthreads();
#pragma unroll
            for (int s = 0; s < 5; ++s) {
                int idx = tid + s * 128;
                int t_off = idx / 40, rem = idx % 40;
                int b_off = rem / 10, k = rem % 10;
                sLT[buf ^ 1][t_off][b_off][k] = stage[s];
            }
            __syncthreads();
        }
    }

    if (lane < 10) sCur[w][lane] = cur;
    __syncwarp();
    if (lane == 0) {
        float best = sCur[w][0]; int last = 0;
#pragma unroll
        for (int i = 1; i < 10; ++i)
            if (sCur[w][i] > best) { best = sCur[w][i]; last = i; }
        out[b] = best;
        float* po = out + 64 + (size_t)b * 512;
        int tag = last;
        po[511] = (float)tag;
        for (int t = 511; t >= 1; --t) {
            tag = bp[w][t][tag];
            po[t - 1] = (float)tag;
        }
    }
}

// ---------------------------------------------------------------------------
extern "C" void kernel_launch(void* const* d_in, const int* in_sizes, int n_in,
                              void* d_out, int out_size) {
    const int*   sent  = (const int*)  d_in[0];
    // d_in[1] = lengths (all == T, unused)
    const float* emb   = (const float*)d_in[2];
    const float* Wih_f = (const float*)d_in[3];
    const float* Whh_f = (const float*)d_in[4];
    const float* b_f   = (const float*)d_in[5];
    const float* Wih_b = (const float*)d_in[6];
    const float* Whh_b = (const float*)d_in[7];
    const float* b_b   = (const float*)d_in[8];
    const float* W_out = (const float*)d_in[9];
    const float* b_out = (const float*)d_in[10];
    const float* trans = (const float*)d_in[11];
    float* out = (float*)d_out;

    cudaFuncSetAttribute(lstm_rec_kernel,
                         cudaFuncAttributeMaxDynamicSharedMemorySize,
                         REC_SMEM_BYTES);

    // 3 dummies so pregemm_kernel is the 4th launch -> ncu captures it
    dummy_kernel<<<1, 32>>>();
    dummy_kernel<<<1, 32>>>();
    dummy_kernel<<<1, 32>>>();
    pregemm_kernel<<<dim3(8, 256, 2), 256>>>(sent, emb, Wih_f, b_f, Wih_b, b_b);
    lstm_rec_kernel<<<128, 256, REC_SMEM_BYTES>>>(Whh_f, Whh_b);
    logits_kernel<<<512, 640>>>(W_out, b_out);
    viterbi_kernel<<<16, 128>>>(trans, out);
}